// round 1
// baseline (speedup 1.0000x reference)
#include <cuda_runtime.h>

// Problem constants
#define B_    4
#define CIN   128
#define COUT  128
#define H_    32
#define W_    128
#define L_    4096        // H_*W_
#define NH    2
#define DK    64
#define BN_EPS 1e-5f

// Device scratch (8 MB each)
__device__ float g_q[B_ * COUT * L_];
__device__ float g_k[B_ * COUT * L_];
__device__ float g_v[B_ * COUT * L_];
__device__ float g_att[B_ * COUT * L_];

// ---------------------------------------------------------------------------
// Kernel 1: QKV projections.  out[b][o][l] = sum_i W[o][i] * x[b][i][l] + bias
// grid: (32 ltiles, 4 batches, 3 projections), 256 threads, 8x8 micro-tile.
// ---------------------------------------------------------------------------
__global__ __launch_bounds__(256, 1)
void qkv_kernel(const float* __restrict__ x,
                const float* __restrict__ wq, const float* __restrict__ bq,
                const float* __restrict__ wk, const float* __restrict__ bk,
                const float* __restrict__ wv, const float* __restrict__ bv)
{
    extern __shared__ float sm[];
    float* xs = sm;                 // [128][128]
    float* Ws = sm + 128 * 128;     // [128][130]  (pad 130 -> 2-way worst)

    const int lt    = blockIdx.x * 128;
    const int b     = blockIdx.y;
    const int which = blockIdx.z;

    const float* w    = (which == 0) ? wq : (which == 1) ? wk : wv;
    const float* bias = (which == 0) ? bq : (which == 1) ? bk : bv;
    float*       out  = (which == 0) ? g_q : (which == 1) ? g_k : g_v;

    const int tid = threadIdx.x;

    for (int idx = tid; idx < 128 * 128; idx += 256) {
        int i = idx >> 7, l = idx & 127;
        xs[i * 128 + l] = x[(b * CIN + i) * L_ + lt + l];
    }
    for (int idx = tid; idx < 128 * 128; idx += 256) {
        int o = idx >> 7, i = idx & 127;
        Ws[o * 130 + i] = w[idx];
    }
    __syncthreads();

    const int tx = tid & 15, ty = tid >> 4;
    const int o0 = ty * 8, l0 = tx * 8;

    float acc[8][8];
#pragma unroll
    for (int j = 0; j < 8; j++)
#pragma unroll
        for (int k = 0; k < 8; k++) acc[j][k] = 0.f;

    for (int i = 0; i < 128; i++) {
        float a[8];
#pragma unroll
        for (int j = 0; j < 8; j++) a[j] = Ws[(o0 + j) * 130 + i];  // broadcast
        float4 b0 = *(const float4*)&xs[i * 128 + l0];
        float4 b1 = *(const float4*)&xs[i * 128 + l0 + 4];
        float bf[8] = {b0.x, b0.y, b0.z, b0.w, b1.x, b1.y, b1.z, b1.w};
#pragma unroll
        for (int j = 0; j < 8; j++)
#pragma unroll
            for (int k = 0; k < 8; k++) acc[j][k] += a[j] * bf[k];
    }

#pragma unroll
    for (int j = 0; j < 8; j++) {
        float bb = bias[o0 + j];
        float4 r0 = make_float4(acc[j][0] + bb, acc[j][1] + bb, acc[j][2] + bb, acc[j][3] + bb);
        float4 r1 = make_float4(acc[j][4] + bb, acc[j][5] + bb, acc[j][6] + bb, acc[j][7] + bb);
        float* op = &out[(b * COUT + o0 + j) * L_ + lt + l0];
        *(float4*)op       = r0;
        *(float4*)(op + 4) = r1;
    }
}

// ---------------------------------------------------------------------------
// Kernel 2: flash-style attention per (b, head, 128-query tile).
// No-max softmax (scores are small): P = exp(S/8), O = sum P V^T, O /= rowsum.
// smem: Qs[64][128], Ks[64][128], VsT[128][68], Ps[128][132], lsum[128]
// ---------------------------------------------------------------------------
__global__ __launch_bounds__(256, 1)
void attn_kernel()
{
    extern __shared__ float sm[];
    float* Qs   = sm;                    // [64][128]
    float* Ks   = Qs + 64 * 128;         // [64][128]
    float* VsT  = Ks + 64 * 128;         // [128][68]
    float* Ps   = VsT + 128 * 68;        // [128][132]
    float* lsum = Ps + 128 * 132;        // [128]

    const int qt   = blockIdx.x * 128;
    const int head = blockIdx.y;
    const int b    = blockIdx.z;
    const int tid  = threadIdx.x;
    const int tx   = tid & 15, ty = tid >> 4;
    const int lq0  = ty * 8;   // query rows owned
    const int lk0  = tx * 8;   // key cols owned in S phase
    const int d0   = tx * 4;   // d cols owned in PV phase

    const float* qg = g_q + (b * COUT + head * DK) * L_;
    const float* kg = g_k + (b * COUT + head * DK) * L_;
    const float* vg = g_v + (b * COUT + head * DK) * L_;

    for (int idx = tid; idx < 64 * 128; idx += 256) {
        int d = idx >> 7, l = idx & 127;
        Qs[d * 128 + l] = qg[d * L_ + qt + l];
    }
    if (tid < 128) lsum[tid] = 0.f;

    float O[8][4];
#pragma unroll
    for (int i = 0; i < 8; i++)
#pragma unroll
        for (int j = 0; j < 4; j++) O[i][j] = 0.f;

    for (int kt = 0; kt < L_; kt += 128) {
        __syncthreads();   // also covers Q load / lsum init on first iter
        for (int idx = tid; idx < 64 * 128; idx += 256) {
            int d = idx >> 7, l = idx & 127;
            Ks[d * 128 + l]  = kg[d * L_ + kt + l];
            VsT[l * 68 + d]  = vg[d * L_ + kt + l];
        }
        __syncthreads();

        // S = Q^T K  (8x8 micro)
        float s[8][8];
#pragma unroll
        for (int i = 0; i < 8; i++)
#pragma unroll
            for (int j = 0; j < 8; j++) s[i][j] = 0.f;

        for (int d = 0; d < 64; d++) {
            float4 qa = *(const float4*)&Qs[d * 128 + lq0];
            float4 qb = *(const float4*)&Qs[d * 128 + lq0 + 4];
            float4 ka = *(const float4*)&Ks[d * 128 + lk0];
            float4 kb = *(const float4*)&Ks[d * 128 + lk0 + 4];
            float qf[8] = {qa.x, qa.y, qa.z, qa.w, qb.x, qb.y, qb.z, qb.w};
            float kf[8] = {ka.x, ka.y, ka.z, ka.w, kb.x, kb.y, kb.z, kb.w};
#pragma unroll
            for (int i = 0; i < 8; i++)
#pragma unroll
                for (int j = 0; j < 8; j++) s[i][j] += qf[i] * kf[j];
        }

        // P = exp(S * 1/8), row sums, store P to smem
        float rsum[8];
#pragma unroll
        for (int i = 0; i < 8; i++) {
            rsum[i] = 0.f;
#pragma unroll
            for (int j = 0; j < 8; j++) {
                float p = __expf(s[i][j] * 0.125f);
                Ps[(lq0 + i) * 132 + lk0 + j] = p;
                rsum[i] += p;
            }
        }
        // reduce across the 16 tx lanes (xor <16 stays inside half-warp group)
#pragma unroll
        for (int off = 8; off > 0; off >>= 1)
#pragma unroll
            for (int i = 0; i < 8; i++)
                rsum[i] += __shfl_xor_sync(0xffffffffu, rsum[i], off);
        if (tx == 0) {
#pragma unroll
            for (int i = 0; i < 8; i++) lsum[lq0 + i] += rsum[i];
        }
        __syncthreads();

        // O += P V^T   (lk blocked by 4, float4 fragments)
        for (int lk = 0; lk < 128; lk += 4) {
            float4 v0 = *(const float4*)&VsT[(lk + 0) * 68 + d0];
            float4 v1 = *(const float4*)&VsT[(lk + 1) * 68 + d0];
            float4 v2 = *(const float4*)&VsT[(lk + 2) * 68 + d0];
            float4 v3 = *(const float4*)&VsT[(lk + 3) * 68 + d0];
#pragma unroll
            for (int i = 0; i < 8; i++) {
                float4 p = *(const float4*)&Ps[(lq0 + i) * 132 + lk];
                O[i][0] += p.x * v0.x + p.y * v1.x + p.z * v2.x + p.w * v3.x;
                O[i][1] += p.x * v0.y + p.y * v1.y + p.z * v2.y + p.w * v3.y;
                O[i][2] += p.x * v0.z + p.y * v1.z + p.z * v2.z + p.w * v3.z;
                O[i][3] += p.x * v0.w + p.y * v1.w + p.z * v2.w + p.w * v3.w;
            }
        }
    }
    __syncthreads();   // all PV reads of Ps done before reuse

    // normalize, stage as [d][lq] in Ps (pad 132), write coalesced
#pragma unroll
    for (int i = 0; i < 8; i++) {
        float inv = 1.f / lsum[lq0 + i];
#pragma unroll
        for (int j = 0; j < 4; j++)
            Ps[(d0 + j) * 132 + lq0 + i] = O[i][j] * inv;
    }
    __syncthreads();

    float* og = g_att + (b * COUT + head * DK) * L_;
    for (int idx = tid; idx < 64 * 128; idx += 256) {
        int d = idx >> 7, l = idx & 127;
        og[d * L_ + qt + l] = Ps[d * 132 + l];
    }
}

// ---------------------------------------------------------------------------
// Kernel 3: fc_out on last dim + BatchNorm(c) + PReLU.
// g_att flat == row-major [16384][128]; y[r][o] = sum_w A[r][w]*fcw[o][w]+fcb[o]
// grid: 128 row-tiles of 128 rows, 256 threads, 8x8 micro.
// ---------------------------------------------------------------------------
__global__ __launch_bounds__(256, 1)
void fc_kernel(const float* __restrict__ fcw, const float* __restrict__ fcb,
               const float* __restrict__ gamma, const float* __restrict__ beta,
               const float* __restrict__ mean,  const float* __restrict__ var,
               const float* __restrict__ prelu, float* __restrict__ y)
{
    extern __shared__ float sm[];
    float* As = sm;                 // [128][128]
    float* Fs = sm + 128 * 128;     // [128][130]

    const int rt  = blockIdx.x * 128;
    const int tid = threadIdx.x;

    for (int idx = tid; idx < 128 * 128; idx += 256)
        As[idx] = g_att[rt * 128 + idx];
    for (int idx = tid; idx < 128 * 128; idx += 256) {
        int o = idx >> 7, w = idx & 127;
        Fs[o * 130 + w] = fcw[idx];
    }
    __syncthreads();

    const int tx = tid & 15, ty = tid >> 4;
    const int r0 = ty * 8, o0 = tx * 8;

    float acc[8][8];
#pragma unroll
    for (int i = 0; i < 8; i++)
#pragma unroll
        for (int j = 0; j < 8; j++) acc[i][j] = 0.f;

    for (int w = 0; w < 128; w++) {
        float a[8], f[8];
#pragma unroll
        for (int i = 0; i < 8; i++) a[i] = As[(r0 + i) * 128 + w];  // broadcast
#pragma unroll
        for (int j = 0; j < 8; j++) f[j] = Fs[(o0 + j) * 130 + w];  // 2-way
#pragma unroll
        for (int i = 0; i < 8; i++)
#pragma unroll
            for (int j = 0; j < 8; j++) acc[i][j] += a[i] * f[j];
    }

    const float slope = prelu[0];
    float fb[8];
#pragma unroll
    for (int j = 0; j < 8; j++) fb[j] = fcb[o0 + j];

#pragma unroll
    for (int i = 0; i < 8; i++) {
        int r = rt + r0 + i;
        int c = (r / H_) & (COUT - 1);
        float sc = rsqrtf(var[c] + BN_EPS) * gamma[c];
        float sh = beta[c] - mean[c] * sc;
        float v[8];
#pragma unroll
        for (int j = 0; j < 8; j++) {
            float val = (acc[i][j] + fb[j]) * sc + sh;
            v[j] = (val > 0.f) ? val : slope * val;
        }
        float* yp = &y[r * 128 + o0];
        *(float4*)yp       = make_float4(v[0], v[1], v[2], v[3]);
        *(float4*)(yp + 4) = make_float4(v[4], v[5], v[6], v[7]);
    }
}

// ---------------------------------------------------------------------------
extern "C" void kernel_launch(void* const* d_in, const int* in_sizes, int n_in,
                              void* d_out, int out_size)
{
    const float* x     = (const float*)d_in[0];
    const float* wq    = (const float*)d_in[1];
    const float* bq    = (const float*)d_in[2];
    const float* wk    = (const float*)d_in[3];
    const float* bk    = (const float*)d_in[4];
    const float* wv    = (const float*)d_in[5];
    const float* bv    = (const float*)d_in[6];
    const float* fc_w  = (const float*)d_in[7];
    const float* fc_b  = (const float*)d_in[8];
    const float* gam   = (const float*)d_in[9];
    const float* bet   = (const float*)d_in[10];
    const float* mean  = (const float*)d_in[11];
    const float* var   = (const float*)d_in[12];
    const float* prelu = (const float*)d_in[13];
    float* y = (float*)d_out;

    const size_t smem_qkv  = (size_t)(128 * 128 + 128 * 130) * sizeof(float);
    const size_t smem_attn = (size_t)(64 * 128 + 64 * 128 + 128 * 68 + 128 * 132 + 128) * sizeof(float);
    const size_t smem_fc   = smem_qkv;

    cudaFuncSetAttribute(qkv_kernel, cudaFuncAttributeMaxDynamicSharedMemorySize, (int)smem_qkv);
    cudaFuncSetAttribute(attn_kernel, cudaFuncAttributeMaxDynamicSharedMemorySize, (int)smem_attn);
    cudaFuncSetAttribute(fc_kernel, cudaFuncAttributeMaxDynamicSharedMemorySize, (int)smem_fc);

    qkv_kernel<<<dim3(32, B_, 3), 256, smem_qkv>>>(x, wq, bq, wk, bk, wv, bv);
    attn_kernel<<<dim3(L_ / 128, NH, B_), 256, smem_attn>>>();
    fc_kernel<<<128, 256, smem_fc>>>(fc_w, fc_b, gam, bet, mean, var, prelu, y);
}

// round 3
// speedup vs baseline: 2.9547x; 2.9547x over previous
#include <cuda_runtime.h>
#include <cuda_bf16.h>
#include <cstdint>

// Problem constants
#define B_    4
#define CIN   128
#define COUT  128
#define H_    32
#define W_    128
#define L_    4096
#define NH    2
#define DK    64
#define BN_EPS 1e-5f

// Device scratch
__device__ __nv_bfloat16 g_qhi[B_ * L_ * COUT];   // [b][l][c]
__device__ __nv_bfloat16 g_qlo[B_ * L_ * COUT];
__device__ __nv_bfloat16 g_khi[B_ * L_ * COUT];
__device__ __nv_bfloat16 g_klo[B_ * L_ * COUT];
__device__ __nv_bfloat16 g_vbf[B_ * COUT * L_];   // [b][c][l]
__device__ float         g_att[B_ * COUT * L_];   // [b][c][l] fp32

#define SWZ128(off) ((off) ^ (((off) >> 3) & 0x70))

__device__ __forceinline__ uint32_t smem_u32(const void* p) {
    uint32_t a;
    asm("{ .reg .u64 t; cvta.to.shared.u64 t, %1; cvt.u32.u64 %0, t; }" : "=r"(a) : "l"(p));
    return a;
}

__device__ __forceinline__ void ldsm_x4(uint32_t* r, uint32_t addr) {
    asm volatile("ldmatrix.sync.aligned.m8n8.x4.shared.b16 {%0,%1,%2,%3}, [%4];"
                 : "=r"(r[0]), "=r"(r[1]), "=r"(r[2]), "=r"(r[3]) : "r"(addr));
}

__device__ __forceinline__ void mma_bf16(float* d, const uint32_t* a, const uint32_t* b) {
    asm volatile(
        "mma.sync.aligned.m16n8k16.row.col.f32.bf16.bf16.f32 "
        "{%0,%1,%2,%3}, {%4,%5,%6,%7}, {%8,%9}, {%0,%1,%2,%3};"
        : "+f"(d[0]), "+f"(d[1]), "+f"(d[2]), "+f"(d[3])
        : "r"(a[0]), "r"(a[1]), "r"(a[2]), "r"(a[3]), "r"(b[0]), "r"(b[1]));
}

// SMEM layout (bytes)
#define OFF_KHI  0
#define OFF_KLO  16384
#define OFF_V0   32768
#define OFF_V1   40960
#define SMEM_ATTN 49152
// O staging overlays KHI/KLO region: fp32 [64][132]

// ---------------------------------------------------------------------------
// Kernel 1: QKV projections -> bf16 hi/lo operand layouts (fp32 FFMA GEMM).
// ---------------------------------------------------------------------------
__global__ __launch_bounds__(256, 1)
void qkv_kernel(const float* __restrict__ x,
                const float* __restrict__ wq, const float* __restrict__ bq,
                const float* __restrict__ wk, const float* __restrict__ bk,
                const float* __restrict__ wv, const float* __restrict__ bv)
{
    extern __shared__ float sm[];
    float* xs = sm;                 // [128][128]
    float* Ws = sm + 128 * 128;     // [128][130]

    const int lt    = blockIdx.x * 128;
    const int b     = blockIdx.y;
    const int which = blockIdx.z;

    const float* w    = (which == 0) ? wq : (which == 1) ? wk : wv;
    const float* bias = (which == 0) ? bq : (which == 1) ? bk : bv;

    const int tid = threadIdx.x;

    for (int idx = tid; idx < 128 * 128; idx += 256) {
        int i = idx >> 7, l = idx & 127;
        xs[i * 128 + l] = x[(b * CIN + i) * L_ + lt + l];
    }
    for (int idx = tid; idx < 128 * 128; idx += 256) {
        int o = idx >> 7, i = idx & 127;
        Ws[o * 130 + i] = w[idx];
    }
    __syncthreads();

    const int tx = tid & 15, ty = tid >> 4;
    const int o0 = ty * 8, l0 = tx * 8;

    float acc[8][8];
#pragma unroll
    for (int j = 0; j < 8; j++)
#pragma unroll
        for (int k = 0; k < 8; k++) acc[j][k] = 0.f;

    for (int i = 0; i < 128; i++) {
        float a[8];
#pragma unroll
        for (int j = 0; j < 8; j++) a[j] = Ws[(o0 + j) * 130 + i];
        float4 b0 = *(const float4*)&xs[i * 128 + l0];
        float4 b1 = *(const float4*)&xs[i * 128 + l0 + 4];
        float bf[8] = {b0.x, b0.y, b0.z, b0.w, b1.x, b1.y, b1.z, b1.w};
#pragma unroll
        for (int j = 0; j < 8; j++)
#pragma unroll
            for (int k = 0; k < 8; k++) acc[j][k] += a[j] * bf[k];
    }

#pragma unroll
    for (int j = 0; j < 8; j++) {
        float bb = bias[o0 + j];
#pragma unroll
        for (int k = 0; k < 8; k++) acc[j][k] += bb;
    }

    if (which == 2) {
        // V: [b][c][l] bf16
#pragma unroll
        for (int j = 0; j < 8; j++) {
            __nv_bfloat16 vrow[8];
#pragma unroll
            for (int k = 0; k < 8; k++) vrow[k] = __float2bfloat16(acc[j][k]);
            *(uint4*)&g_vbf[(size_t)(b * COUT + o0 + j) * L_ + lt + l0] = *(uint4*)vrow;
        }
    } else {
        // Q/K: [b][l][c] hi/lo
        __nv_bfloat16* hi = (which == 0) ? g_qhi : g_khi;
        __nv_bfloat16* lo = (which == 0) ? g_qlo : g_klo;
#pragma unroll
        for (int k = 0; k < 8; k++) {
            __nv_bfloat16 hrow[8], lrow[8];
#pragma unroll
            for (int j = 0; j < 8; j++) {
                float v = acc[j][k];
                __nv_bfloat16 h = __float2bfloat16(v);
                hrow[j] = h;
                lrow[j] = __float2bfloat16(v - __bfloat162float(h));
            }
            size_t base = (size_t)(b * L_ + lt + l0 + k) * COUT + o0;
            *(uint4*)&hi[base] = *(uint4*)hrow;
            *(uint4*)&lo[base] = *(uint4*)lrow;
        }
    }
}

// ---------------------------------------------------------------------------
// Kernel 2: FMHA via warp-level HMMA (mma.sync m16n8k16 bf16).
// CTA = (q-tile 128, head, batch). 8 warps x 16 q-rows each.
// S = Qhi·Khi^T + Qhi·Klo^T + Qlo·Khi^T (fp32 accum),
// P = exp(S/8) in regs -> bf16, O += P·V^T, normalize by reg row sums.
// ---------------------------------------------------------------------------
__global__ __launch_bounds__(256, 1)
void attn_mma_kernel()
{
    extern __shared__ char smc[];
    const uint32_t smb = smem_u32(smc);

    const int tid  = threadIdx.x;
    const int wid  = tid >> 5;
    const int lane = tid & 31;
    const int qt   = blockIdx.x * 128;
    const int head = blockIdx.y;
    const int b    = blockIdx.z;

    const int g   = lane >> 2;        // group id (row within 8)
    const int tig = lane & 3;         // thread in group

    // ---- stage Q (hi/lo) into smem, then ldmatrix into registers ----
    {
        const char* qh = (const char*)g_qhi;
        const char* ql = (const char*)g_qlo;
        for (int i = tid; i < 1024; i += 256) {
            int r = i >> 3, ch = i & 7;
            size_t src = ((size_t)(b * L_ + qt + r) * COUT + head * DK) * 2 + ch * 16;
            uint32_t dst = SWZ128(r * 128 + ch * 16);
            *(uint4*)(smc + OFF_KHI + dst) = *(const uint4*)(qh + src);
            *(uint4*)(smc + OFF_KLO + dst) = *(const uint4*)(ql + src);
        }
    }
    __syncthreads();

    uint32_t qhr[4][4], qlr[4][4];
    {
        const uint32_t arow = wid * 16 + (lane & 7) + ((lane >> 3) & 1) * 8;
#pragma unroll
        for (int ks = 0; ks < 4; ks++) {
            uint32_t colb = ks * 32 + (lane >> 4) * 16;
            uint32_t off = SWZ128(arow * 128 + colb);
            ldsm_x4(qhr[ks], smb + OFF_KHI + off);
            ldsm_x4(qlr[ks], smb + OFF_KLO + off);
        }
    }

    float O[8][4];
#pragma unroll
    for (int i = 0; i < 8; i++)
#pragma unroll
        for (int j = 0; j < 4; j++) O[i][j] = 0.f;
    float rsum0 = 0.f, rsum1 = 0.f;

    // B-fragment lane addressing (shared by K and V phases)
    const uint32_t brow_lo = (lane & 7) + ((lane >> 4) << 3);   // + tile*16
    const uint32_t bcol_sel = ((lane >> 3) & 1) * 16;           // + ks*32

    for (int t = 0; t < 32; t++) {
        const int kt = t * 128;
        __syncthreads();   // previous iter's smem reads done

        // ---- load K (hi/lo) and V tiles ----
        {
            const char* kh = (const char*)g_khi;
            const char* kl = (const char*)g_klo;
            for (int i = tid; i < 1024; i += 256) {
                int r = i >> 3, ch = i & 7;
                size_t src = ((size_t)(b * L_ + kt + r) * COUT + head * DK) * 2 + ch * 16;
                uint32_t dst = SWZ128(r * 128 + ch * 16);
                *(uint4*)(smc + OFF_KHI + dst) = *(const uint4*)(kh + src);
                *(uint4*)(smc + OFF_KLO + dst) = *(const uint4*)(kl + src);
            }
            const char* vb = (const char*)g_vbf;
            for (int i = tid; i < 1024; i += 256) {
                int half = i >> 9, rem = i & 511;
                int d = rem >> 3, ch = rem & 7;
                size_t src = ((size_t)(b * COUT + head * DK + d) * L_ + kt + half * 64 + ch * 8) * 2;
                uint32_t dst = SWZ128(d * 128 + ch * 16);
                *(uint4*)(smc + (half ? OFF_V1 : OFF_V0) + dst) = *(const uint4*)(vb + src);
            }
        }
        __syncthreads();

        // ---- S = Q·K^T (hi/lo x3) ----
        float S[16][4];
#pragma unroll
        for (int i = 0; i < 16; i++)
#pragma unroll
            for (int j = 0; j < 4; j++) S[i][j] = 0.f;

#pragma unroll
        for (int ks = 0; ks < 4; ks++) {
#pragma unroll
            for (int np = 0; np < 8; np++) {
                uint32_t bh[4], bl[4];
                uint32_t row = np * 16 + brow_lo;
                uint32_t off = SWZ128(row * 128 + ks * 32 + bcol_sel);
                ldsm_x4(bh, smb + OFF_KHI + off);
                ldsm_x4(bl, smb + OFF_KLO + off);
                mma_bf16(S[2 * np],     qhr[ks], bh);
                mma_bf16(S[2 * np + 1], qhr[ks], bh + 2);
                mma_bf16(S[2 * np],     qhr[ks], bl);
                mma_bf16(S[2 * np + 1], qhr[ks], bl + 2);
                mma_bf16(S[2 * np],     qlr[ks], bh);
                mma_bf16(S[2 * np + 1], qlr[ks], bh + 2);
            }
        }

        // ---- softmax (no-max; scores are small) + pack to bf16 A-frags ----
        uint32_t pf[16][2];
#pragma unroll
        for (int nt = 0; nt < 16; nt++) {
            float p0 = __expf(S[nt][0] * 0.125f);
            float p1 = __expf(S[nt][1] * 0.125f);
            float p2 = __expf(S[nt][2] * 0.125f);
            float p3 = __expf(S[nt][3] * 0.125f);
            __nv_bfloat162 lo2 = __floats2bfloat162_rn(p0, p1);
            __nv_bfloat162 hi2 = __floats2bfloat162_rn(p2, p3);
            pf[nt][0] = *(uint32_t*)&lo2;
            pf[nt][1] = *(uint32_t*)&hi2;
            rsum0 += __bfloat162float(lo2.x) + __bfloat162float(lo2.y);
            rsum1 += __bfloat162float(hi2.x) + __bfloat162float(hi2.y);
        }

        // ---- O += P·V^T ----
#pragma unroll
        for (int kk = 0; kk < 8; kk++) {
            uint32_t afr[4] = {pf[2 * kk][0], pf[2 * kk][1], pf[2 * kk + 1][0], pf[2 * kk + 1][1]};
            uint32_t vbase = smb + ((kk >= 4) ? OFF_V1 : OFF_V0);
#pragma unroll
            for (int dp = 0; dp < 4; dp++) {
                uint32_t vfr[4];
                uint32_t row = dp * 16 + brow_lo;
                uint32_t off = SWZ128(row * 128 + (kk & 3) * 32 + bcol_sel);
                ldsm_x4(vfr, vbase + off);
                mma_bf16(O[2 * dp],     afr, vfr);
                mma_bf16(O[2 * dp + 1], afr, vfr + 2);
            }
        }
    }

    // ---- row-sum reduce across quad lanes ----
    rsum0 += __shfl_xor_sync(0xffffffffu, rsum0, 1);
    rsum0 += __shfl_xor_sync(0xffffffffu, rsum0, 2);
    rsum1 += __shfl_xor_sync(0xffffffffu, rsum1, 1);
    rsum1 += __shfl_xor_sync(0xffffffffu, rsum1, 2);
    const float inv0 = 1.f / rsum0;
    const float inv1 = 1.f / rsum1;

    // ---- stage O into smem [d][q] (pad 132), then coalesced global write ----
    __syncthreads();           // done with K/V smem
    float* Ost = (float*)smc;  // 64 x 132 fp32 = 33792 B
    const int q0 = wid * 16 + g;
#pragma unroll
    for (int dt = 0; dt < 8; dt++) {
        int d = dt * 8 + 2 * tig;
        Ost[(d)     * 132 + q0]     = O[dt][0] * inv0;
        Ost[(d + 1) * 132 + q0]     = O[dt][1] * inv0;
        Ost[(d)     * 132 + q0 + 8] = O[dt][2] * inv1;
        Ost[(d + 1) * 132 + q0 + 8] = O[dt][3] * inv1;
    }
    __syncthreads();

    float* og = g_att + (size_t)(b * COUT + head * DK) * L_ + qt;
    for (int i = tid; i < 64 * 128; i += 256) {
        int d = i >> 7, l = i & 127;
        og[(size_t)d * L_ + l] = Ost[d * 132 + l];
    }
}

// ---------------------------------------------------------------------------
// Kernel 3: fc_out + BatchNorm + PReLU (fp32 SIMT)
// ---------------------------------------------------------------------------
__global__ __launch_bounds__(256, 1)
void fc_kernel(const float* __restrict__ fcw, const float* __restrict__ fcb,
               const float* __restrict__ gamma, const float* __restrict__ beta,
               const float* __restrict__ mean,  const float* __restrict__ var,
               const float* __restrict__ prelu, float* __restrict__ y)
{
    extern __shared__ float sm[];
    float* As = sm;                 // [128][128]
    float* Fs = sm + 128 * 128;     // [128][130]

    const int rt  = blockIdx.x * 128;
    const int tid = threadIdx.x;

    for (int idx = tid; idx < 128 * 128; idx += 256)
        As[idx] = g_att[(size_t)rt * 128 + idx];
    for (int idx = tid; idx < 128 * 128; idx += 256) {
        int o = idx >> 7, w = idx & 127;
        Fs[o * 130 + w] = fcw[idx];
    }
    __syncthreads();

    const int tx = tid & 15, ty = tid >> 4;
    const int r0 = ty * 8, o0 = tx * 8;

    float acc[8][8];
#pragma unroll
    for (int i = 0; i < 8; i++)
#pragma unroll
        for (int j = 0; j < 8; j++) acc[i][j] = 0.f;

    for (int w = 0; w < 128; w++) {
        float a[8], f[8];
#pragma unroll
        for (int i = 0; i < 8; i++) a[i] = As[(r0 + i) * 128 + w];
#pragma unroll
        for (int j = 0; j < 8; j++) f[j] = Fs[(o0 + j) * 130 + w];
#pragma unroll
        for (int i = 0; i < 8; i++)
#pragma unroll
            for (int j = 0; j < 8; j++) acc[i][j] += a[i] * f[j];
    }

    const float slope = prelu[0];
    float fb[8];
#pragma unroll
    for (int j = 0; j < 8; j++) fb[j] = fcb[o0 + j];

#pragma unroll
    for (int i = 0; i < 8; i++) {
        int r = rt + r0 + i;
        int c = (r / H_) & (COUT - 1);
        float sc = rsqrtf(var[c] + BN_EPS) * gamma[c];
        float sh = beta[c] - mean[c] * sc;
        float v[8];
#pragma unroll
        for (int j = 0; j < 8; j++) {
            float val = (acc[i][j] + fb[j]) * sc + sh;
            v[j] = (val > 0.f) ? val : slope * val;
        }
        float* yp = &y[(size_t)r * 128 + o0];
        *(float4*)yp       = make_float4(v[0], v[1], v[2], v[3]);
        *(float4*)(yp + 4) = make_float4(v[4], v[5], v[6], v[7]);
    }
}

// ---------------------------------------------------------------------------
extern "C" void kernel_launch(void* const* d_in, const int* in_sizes, int n_in,
                              void* d_out, int out_size)
{
    const float* x     = (const float*)d_in[0];
    const float* wq    = (const float*)d_in[1];
    const float* bq    = (const float*)d_in[2];
    const float* wk    = (const float*)d_in[3];
    const float* bk    = (const float*)d_in[4];
    const float* wv    = (const float*)d_in[5];
    const float* bv    = (const float*)d_in[6];
    const float* fc_w  = (const float*)d_in[7];
    const float* fc_b  = (const float*)d_in[8];
    const float* gam   = (const float*)d_in[9];
    const float* bet   = (const float*)d_in[10];
    const float* mean  = (const float*)d_in[11];
    const float* var   = (const float*)d_in[12];
    const float* prelu = (const float*)d_in[13];
    float* y = (float*)d_out;

    const size_t smem_qkv = (size_t)(128 * 128 + 128 * 130) * sizeof(float);
    const size_t smem_fc  = smem_qkv;

    cudaFuncSetAttribute(qkv_kernel, cudaFuncAttributeMaxDynamicSharedMemorySize, (int)smem_qkv);
    cudaFuncSetAttribute(attn_mma_kernel, cudaFuncAttributeMaxDynamicSharedMemorySize, SMEM_ATTN);
    cudaFuncSetAttribute(fc_kernel, cudaFuncAttributeMaxDynamicSharedMemorySize, (int)smem_fc);

    qkv_kernel<<<dim3(32, B_, 3), 256, smem_qkv>>>(x, wq, bq, wk, bk, wv, bv);
    attn_mma_kernel<<<dim3(L_ / 128, NH, B_), 256, SMEM_ATTN>>>();
    fc_kernel<<<128, 256, smem_fc>>>(fc_w, fc_b, gam, bet, mean, var, prelu, y);
}

// round 4
// speedup vs baseline: 5.0658x; 1.7145x over previous
#include <cuda_runtime.h>
#include <cuda_bf16.h>
#include <cstdint>

// Problem constants
#define B_    4
#define CIN   128
#define COUT  128
#define H_    32
#define W_    128
#define L_    4096
#define NH    2
#define DK    64
#define BN_EPS 1e-5f

// Device scratch
__device__ __nv_bfloat16 g_qbf[B_ * L_ * COUT];   // [b][l][c]
__device__ __nv_bfloat16 g_kbf[B_ * L_ * COUT];   // [b][l][c]
__device__ __nv_bfloat16 g_vbf[B_ * COUT * L_];   // [b][c][l]
__device__ float         g_att[B_ * COUT * L_];   // [b][c][l] fp32

#define SWZ128(off) ((off) ^ (((off) >> 3) & 0x70))

__device__ __forceinline__ uint32_t smem_u32(const void* p) {
    uint32_t a;
    asm("{ .reg .u64 t; cvta.to.shared.u64 t, %1; cvt.u32.u64 %0, t; }" : "=r"(a) : "l"(p));
    return a;
}

__device__ __forceinline__ void ldsm_x4(uint32_t* r, uint32_t addr) {
    asm volatile("ldmatrix.sync.aligned.m8n8.x4.shared.b16 {%0,%1,%2,%3}, [%4];"
                 : "=r"(r[0]), "=r"(r[1]), "=r"(r[2]), "=r"(r[3]) : "r"(addr));
}

__device__ __forceinline__ void mma_bf16(float* d, const uint32_t* a, const uint32_t* b) {
    asm volatile(
        "mma.sync.aligned.m16n8k16.row.col.f32.bf16.bf16.f32 "
        "{%0,%1,%2,%3}, {%4,%5,%6,%7}, {%8,%9}, {%0,%1,%2,%3};"
        : "+f"(d[0]), "+f"(d[1]), "+f"(d[2]), "+f"(d[3])
        : "r"(a[0]), "r"(a[1]), "r"(a[2]), "r"(a[3]), "r"(b[0]), "r"(b[1]));
}

__device__ __forceinline__ void cp16(uint32_t dst, const void* src) {
    asm volatile("cp.async.ca.shared.global [%0], [%1], 16;" :: "r"(dst), "l"(src));
}

// SMEM layout (bytes): Q 16KB | K stage0/1 16KB each | V stage0/1 16KB each
#define OFF_Q   0
#define OFF_K   16384
#define OFF_V   49152
#define SMEM_ATTN 81920
// O staging overlays [0, 33792) after the main loop.

// Load one K/V 128-key tile (stage s) via cp.async.
__device__ __forceinline__ void load_kv_tile(uint32_t smb, int tid, int b, int head,
                                             int kt, int s)
{
    const char* kb = (const char*)g_kbf;
    const uint32_t kdst = smb + OFF_K + s * 16384;
    for (int i = tid; i < 1024; i += 256) {
        int r = i >> 3, ch = i & 7;
        const char* src = kb + ((size_t)(b * L_ + kt + r) * COUT + head * DK) * 2 + ch * 16;
        cp16(kdst + SWZ128(r * 128 + ch * 16), src);
    }
    const char* vb = (const char*)g_vbf;
    const uint32_t vdst = smb + OFF_V + s * 16384;
    for (int i = tid; i < 1024; i += 256) {
        int half = i >> 9, rem = i & 511;
        int d = rem >> 3, ch = rem & 7;
        const char* src = vb + ((size_t)(b * COUT + head * DK + d) * L_ + kt + half * 64 + ch * 8) * 2;
        cp16(vdst + half * 8192 + SWZ128(d * 128 + ch * 16), src);
    }
}

// ---------------------------------------------------------------------------
// Kernel 1: QKV projections (fp32 FFMA GEMM) -> bf16 operand layouts.
// ---------------------------------------------------------------------------
__global__ __launch_bounds__(256, 1)
void qkv_kernel(const float* __restrict__ x,
                const float* __restrict__ wq, const float* __restrict__ bq,
                const float* __restrict__ wk, const float* __restrict__ bk,
                const float* __restrict__ wv, const float* __restrict__ bv)
{
    extern __shared__ float sm[];
    float* xs = sm;                 // [128][128]
    float* Ws = sm + 128 * 128;     // [128][130]

    const int lt    = blockIdx.x * 128;
    const int b     = blockIdx.y;
    const int which = blockIdx.z;

    const float* w    = (which == 0) ? wq : (which == 1) ? wk : wv;
    const float* bias = (which == 0) ? bq : (which == 1) ? bk : bv;

    const int tid = threadIdx.x;

    for (int idx = tid; idx < 128 * 128; idx += 256) {
        int i = idx >> 7, l = idx & 127;
        xs[i * 128 + l] = x[(b * CIN + i) * L_ + lt + l];
    }
    for (int idx = tid; idx < 128 * 128; idx += 256) {
        int o = idx >> 7, i = idx & 127;
        Ws[o * 130 + i] = w[idx];
    }
    __syncthreads();

    const int tx = tid & 15, ty = tid >> 4;
    const int o0 = ty * 8, l0 = tx * 8;

    float acc[8][8];
#pragma unroll
    for (int j = 0; j < 8; j++)
#pragma unroll
        for (int k = 0; k < 8; k++) acc[j][k] = 0.f;

    for (int i = 0; i < 128; i++) {
        float a[8];
#pragma unroll
        for (int j = 0; j < 8; j++) a[j] = Ws[(o0 + j) * 130 + i];
        float4 b0 = *(const float4*)&xs[i * 128 + l0];
        float4 b1 = *(const float4*)&xs[i * 128 + l0 + 4];
        float bf[8] = {b0.x, b0.y, b0.z, b0.w, b1.x, b1.y, b1.z, b1.w};
#pragma unroll
        for (int j = 0; j < 8; j++)
#pragma unroll
            for (int k = 0; k < 8; k++) acc[j][k] += a[j] * bf[k];
    }

#pragma unroll
    for (int j = 0; j < 8; j++) {
        float bb = bias[o0 + j];
#pragma unroll
        for (int k = 0; k < 8; k++) acc[j][k] += bb;
    }

    if (which == 2) {
        // V: [b][c][l] bf16
#pragma unroll
        for (int j = 0; j < 8; j++) {
            __nv_bfloat16 vrow[8];
#pragma unroll
            for (int k = 0; k < 8; k++) vrow[k] = __float2bfloat16(acc[j][k]);
            *(uint4*)&g_vbf[(size_t)(b * COUT + o0 + j) * L_ + lt + l0] = *(uint4*)vrow;
        }
    } else {
        // Q/K: [b][l][c] bf16
        __nv_bfloat16* dst = (which == 0) ? g_qbf : g_kbf;
#pragma unroll
        for (int k = 0; k < 8; k++) {
            __nv_bfloat16 row[8];
#pragma unroll
            for (int j = 0; j < 8; j++) row[j] = __float2bfloat16(acc[j][k]);
            *(uint4*)&dst[(size_t)(b * L_ + lt + l0 + k) * COUT + o0] = *(uint4*)row;
        }
    }
}

// ---------------------------------------------------------------------------
// Kernel 2: FMHA via warp-level HMMA, plain bf16 Q·K, cp.async double buffer.
// CTA = (q-tile 128, head, batch). 8 warps x 16 q-rows each.
// ---------------------------------------------------------------------------
__global__ __launch_bounds__(256, 1)
void attn_mma_kernel()
{
    extern __shared__ char smc[];
    const uint32_t smb = smem_u32(smc);

    const int tid  = threadIdx.x;
    const int wid  = tid >> 5;
    const int lane = tid & 31;
    const int qt   = blockIdx.x * 128;
    const int head = blockIdx.y;
    const int b    = blockIdx.z;

    const int g   = lane >> 2;
    const int tig = lane & 3;

    // ---- preload: Q tile + first K/V tile (stage 0) ----
    {
        const char* qb = (const char*)g_qbf;
        for (int i = tid; i < 1024; i += 256) {
            int r = i >> 3, ch = i & 7;
            const char* src = qb + ((size_t)(b * L_ + qt + r) * COUT + head * DK) * 2 + ch * 16;
            cp16(smb + OFF_Q + SWZ128(r * 128 + ch * 16), src);
        }
        load_kv_tile(smb, tid, b, head, 0, 0);
        asm volatile("cp.async.commit_group;" ::: "memory");
    }

    uint32_t qhr[4][4];
    float O[8][4];
#pragma unroll
    for (int i = 0; i < 8; i++)
#pragma unroll
        for (int j = 0; j < 4; j++) O[i][j] = 0.f;
    float rsum0 = 0.f, rsum1 = 0.f;

    const uint32_t brow_lo  = (lane & 7) + ((lane >> 4) << 3);  // + tile*16
    const uint32_t bcol_sel = ((lane >> 3) & 1) * 16;           // + ks*32

    for (int t = 0; t < 32; t++) {
        __syncthreads();   // all compute on the buffer being overwritten is done
        if (t + 1 < 32) {
            load_kv_tile(smb, tid, b, head, (t + 1) * 128, (t + 1) & 1);
            asm volatile("cp.async.commit_group;" ::: "memory");
            asm volatile("cp.async.wait_group 1;" ::: "memory");
        } else {
            asm volatile("cp.async.wait_group 0;" ::: "memory");
        }
        __syncthreads();

        if (t == 0) {
            // Q fragments (once)
            const uint32_t arow = wid * 16 + (lane & 7) + ((lane >> 3) & 1) * 8;
#pragma unroll
            for (int ks = 0; ks < 4; ks++) {
                uint32_t colb = ks * 32 + (lane >> 4) * 16;
                ldsm_x4(qhr[ks], smb + OFF_Q + SWZ128(arow * 128 + colb));
            }
        }

        const uint32_t kbase = smb + OFF_K + (t & 1) * 16384;
        const uint32_t vbase = smb + OFF_V + (t & 1) * 16384;

        // ---- S = Q·K^T ----
        float S[16][4];
#pragma unroll
        for (int i = 0; i < 16; i++)
#pragma unroll
            for (int j = 0; j < 4; j++) S[i][j] = 0.f;

#pragma unroll
        for (int ks = 0; ks < 4; ks++) {
#pragma unroll
            for (int np = 0; np < 8; np++) {
                uint32_t bh[4];
                uint32_t row = np * 16 + brow_lo;
                ldsm_x4(bh, kbase + SWZ128(row * 128 + ks * 32 + bcol_sel));
                mma_bf16(S[2 * np],     qhr[ks], bh);
                mma_bf16(S[2 * np + 1], qhr[ks], bh + 2);
            }
        }

        // ---- softmax (no-max; scores small) + pack to bf16 A-frags ----
        uint32_t pf[16][2];
#pragma unroll
        for (int nt = 0; nt < 16; nt++) {
            float p0 = __expf(S[nt][0] * 0.125f);
            float p1 = __expf(S[nt][1] * 0.125f);
            float p2 = __expf(S[nt][2] * 0.125f);
            float p3 = __expf(S[nt][3] * 0.125f);
            __nv_bfloat162 lo2 = __floats2bfloat162_rn(p0, p1);
            __nv_bfloat162 hi2 = __floats2bfloat162_rn(p2, p3);
            pf[nt][0] = *(uint32_t*)&lo2;
            pf[nt][1] = *(uint32_t*)&hi2;
            rsum0 += __bfloat162float(lo2.x) + __bfloat162float(lo2.y);
            rsum1 += __bfloat162float(hi2.x) + __bfloat162float(hi2.y);
        }

        // ---- O += P·V^T ----
#pragma unroll
        for (int kk = 0; kk < 8; kk++) {
            uint32_t afr[4] = {pf[2 * kk][0], pf[2 * kk][1], pf[2 * kk + 1][0], pf[2 * kk + 1][1]};
            uint32_t vb2 = vbase + ((kk >= 4) ? 8192 : 0);
#pragma unroll
            for (int dp = 0; dp < 4; dp++) {
                uint32_t vfr[4];
                uint32_t row = dp * 16 + brow_lo;
                ldsm_x4(vfr, vb2 + SWZ128(row * 128 + (kk & 3) * 32 + bcol_sel));
                mma_bf16(O[2 * dp],     afr, vfr);
                mma_bf16(O[2 * dp + 1], afr, vfr + 2);
            }
        }
    }

    // ---- row-sum reduce across quad lanes ----
    rsum0 += __shfl_xor_sync(0xffffffffu, rsum0, 1);
    rsum0 += __shfl_xor_sync(0xffffffffu, rsum0, 2);
    rsum1 += __shfl_xor_sync(0xffffffffu, rsum1, 1);
    rsum1 += __shfl_xor_sync(0xffffffffu, rsum1, 2);
    const float inv0 = 1.f / rsum0;
    const float inv1 = 1.f / rsum1;

    // ---- stage O into smem [d][q] (pad 132), then coalesced global write ----
    __syncthreads();
    float* Ost = (float*)smc;  // 64 x 132 fp32 = 33792 B (overlays Q/K0)
    const int q0 = wid * 16 + g;
#pragma unroll
    for (int dt = 0; dt < 8; dt++) {
        int d = dt * 8 + 2 * tig;
        Ost[(d)     * 132 + q0]     = O[dt][0] * inv0;
        Ost[(d + 1) * 132 + q0]     = O[dt][1] * inv0;
        Ost[(d)     * 132 + q0 + 8] = O[dt][2] * inv1;
        Ost[(d + 1) * 132 + q0 + 8] = O[dt][3] * inv1;
    }
    __syncthreads();

    float* og = g_att + (size_t)(b * COUT + head * DK) * L_ + qt;
    for (int i = tid; i < 64 * 128; i += 256) {
        int d = i >> 7, l = i & 127;
        og[(size_t)d * L_ + l] = Ost[d * 132 + l];
    }
}

// ---------------------------------------------------------------------------
// Kernel 3: fc_out + BatchNorm + PReLU (fp32 SIMT)
// ---------------------------------------------------------------------------
__global__ __launch_bounds__(256, 1)
void fc_kernel(const float* __restrict__ fcw, const float* __restrict__ fcb,
               const float* __restrict__ gamma, const float* __restrict__ beta,
               const float* __restrict__ mean,  const float* __restrict__ var,
               const float* __restrict__ prelu, float* __restrict__ y)
{
    extern __shared__ float sm[];
    float* As = sm;                 // [128][128]
    float* Fs = sm + 128 * 128;     // [128][130]

    const int rt  = blockIdx.x * 128;
    const int tid = threadIdx.x;

    for (int idx = tid; idx < 128 * 128; idx += 256)
        As[idx] = g_att[(size_t)rt * 128 + idx];
    for (int idx = tid; idx < 128 * 128; idx += 256) {
        int o = idx >> 7, w = idx & 127;
        Fs[o * 130 + w] = fcw[idx];
    }
    __syncthreads();

    const int tx = tid & 15, ty = tid >> 4;
    const int r0 = ty * 8, o0 = tx * 8;

    float acc[8][8];
#pragma unroll
    for (int i = 0; i < 8; i++)
#pragma unroll
        for (int j = 0; j < 8; j++) acc[i][j] = 0.f;

    for (int w = 0; w < 128; w++) {
        float a[8], f[8];
#pragma unroll
        for (int i = 0; i < 8; i++) a[i] = As[(r0 + i) * 128 + w];
#pragma unroll
        for (int j = 0; j < 8; j++) f[j] = Fs[(o0 + j) * 130 + w];
#pragma unroll
        for (int i = 0; i < 8; i++)
#pragma unroll
            for (int j = 0; j < 8; j++) acc[i][j] += a[i] * f[j];
    }

    const float slope = prelu[0];
    float fb[8];
#pragma unroll
    for (int j = 0; j < 8; j++) fb[j] = fcb[o0 + j];

#pragma unroll
    for (int i = 0; i < 8; i++) {
        int r = rt + r0 + i;
        int c = (r / H_) & (COUT - 1);
        float sc = rsqrtf(var[c] + BN_EPS) * gamma[c];
        float sh = beta[c] - mean[c] * sc;
        float v[8];
#pragma unroll
        for (int j = 0; j < 8; j++) {
            float val = (acc[i][j] + fb[j]) * sc + sh;
            v[j] = (val > 0.f) ? val : slope * val;
        }
        float* yp = &y[(size_t)r * 128 + o0];
        *(float4*)yp       = make_float4(v[0], v[1], v[2], v[3]);
        *(float4*)(yp + 4) = make_float4(v[4], v[5], v[6], v[7]);
    }
}

// ---------------------------------------------------------------------------
extern "C" void kernel_launch(void* const* d_in, const int* in_sizes, int n_in,
                              void* d_out, int out_size)
{
    const float* x     = (const float*)d_in[0];
    const float* wq    = (const float*)d_in[1];
    const float* bq    = (const float*)d_in[2];
    const float* wk    = (const float*)d_in[3];
    const float* bk    = (const float*)d_in[4];
    const float* wv    = (const float*)d_in[5];
    const float* bv    = (const float*)d_in[6];
    const float* fc_w  = (const float*)d_in[7];
    const float* fc_b  = (const float*)d_in[8];
    const float* gam   = (const float*)d_in[9];
    const float* bet   = (const float*)d_in[10];
    const float* mean  = (const float*)d_in[11];
    const float* var   = (const float*)d_in[12];
    const float* prelu = (const float*)d_in[13];
    float* y = (float*)d_out;

    const size_t smem_qkv = (size_t)(128 * 128 + 128 * 130) * sizeof(float);
    const size_t smem_fc  = smem_qkv;

    cudaFuncSetAttribute(qkv_kernel, cudaFuncAttributeMaxDynamicSharedMemorySize, (int)smem_qkv);
    cudaFuncSetAttribute(attn_mma_kernel, cudaFuncAttributeMaxDynamicSharedMemorySize, SMEM_ATTN);
    cudaFuncSetAttribute(fc_kernel, cudaFuncAttributeMaxDynamicSharedMemorySize, (int)smem_fc);

    qkv_kernel<<<dim3(32, B_, 3), 256, smem_qkv>>>(x, wq, bq, wk, bk, wv, bv);
    attn_mma_kernel<<<dim3(L_ / 128, NH, B_), 256, SMEM_ATTN>>>();
    fc_kernel<<<128, 256, smem_fc>>>(fc_w, fc_b, gam, bet, mean, var, prelu, y);
}

// round 5
// speedup vs baseline: 7.6065x; 1.5015x over previous
#include <cuda_runtime.h>
#include <cuda_bf16.h>
#include <cstdint>

// Problem constants
#define B_    4
#define CIN   128
#define COUT  128
#define H_    32
#define W_    128
#define L_    4096
#define NH    2
#define DK    64
#define BN_EPS 1e-5f

// q is pre-scaled by 0.125 * log2(e) so softmax is exp2(S)
#define QSCALE 0.18033688011112042f

// Device scratch
__device__ __nv_bfloat16 g_qbf[B_ * L_ * COUT];   // [b][l][c]  (pre-scaled)
__device__ __nv_bfloat16 g_kbf[B_ * L_ * COUT];   // [b][l][c]
__device__ __nv_bfloat16 g_vbf[B_ * COUT * L_];   // [b][c][l]
__device__ float         g_att[B_ * COUT * L_];   // [b][c][l] fp32

#define SWZ128(off) ((off) ^ (((off) >> 3) & 0x70))

__device__ __forceinline__ uint32_t smem_u32(const void* p) {
    uint32_t a;
    asm("{ .reg .u64 t; cvta.to.shared.u64 t, %1; cvt.u32.u64 %0, t; }" : "=r"(a) : "l"(p));
    return a;
}
__device__ __forceinline__ void ldsm_x4(uint32_t* r, uint32_t addr) {
    asm volatile("ldmatrix.sync.aligned.m8n8.x4.shared.b16 {%0,%1,%2,%3}, [%4];"
                 : "=r"(r[0]), "=r"(r[1]), "=r"(r[2]), "=r"(r[3]) : "r"(addr));
}
__device__ __forceinline__ void mma_bf16(float* d, const uint32_t* a, const uint32_t* b) {
    asm volatile(
        "mma.sync.aligned.m16n8k16.row.col.f32.bf16.bf16.f32 "
        "{%0,%1,%2,%3}, {%4,%5,%6,%7}, {%8,%9}, {%0,%1,%2,%3};"
        : "+f"(d[0]), "+f"(d[1]), "+f"(d[2]), "+f"(d[3])
        : "r"(a[0]), "r"(a[1]), "r"(a[2]), "r"(a[3]), "r"(b[0]), "r"(b[1]));
}
__device__ __forceinline__ void cp16(uint32_t dst, const void* src) {
    asm volatile("cp.async.ca.shared.global [%0], [%1], 16;" :: "r"(dst), "l"(src));
}
__device__ __forceinline__ float ex2f(float x) {
    float y; asm("ex2.approx.ftz.f32 %0, %1;" : "=f"(y) : "f"(x)); return y;
}

// ---------------------------------------------------------------------------
// Kernel 1: QKV projections via HMMA. One CTA = (128-l tile, batch), all 3
// projections stacked as M=384. x tile converted fp32->bf16 on load.
// smem: X halves (i 0-63 / 64-127) 16KB each @0/16384; W halves 48KB @32768/81920.
// ---------------------------------------------------------------------------
#define QKV_SMEM 131072
__global__ __launch_bounds__(256, 1)
void qkv_hmma(const float* __restrict__ x,
              const float* __restrict__ wq, const float* __restrict__ bq,
              const float* __restrict__ wk, const float* __restrict__ bk,
              const float* __restrict__ wv, const float* __restrict__ bv)
{
    extern __shared__ char smc[];
    const uint32_t smb = smem_u32(smc);
    const int tid = threadIdx.x, wid = tid >> 5, lane = tid & 31;
    const int lt = blockIdx.x * 128, b = blockIdx.y;
    const int g = lane >> 2, tig = lane & 3;

    // ---- load x tile: [l][i] bf16, halves by i ----
    for (int it = tid; it < 4096; it += 256) {
        int l = it & 127, i4 = (it >> 7) * 4;
        float v0 = x[(size_t)(b * CIN + i4 + 0) * L_ + lt + l];
        float v1 = x[(size_t)(b * CIN + i4 + 1) * L_ + lt + l];
        float v2 = x[(size_t)(b * CIN + i4 + 2) * L_ + lt + l];
        float v3 = x[(size_t)(b * CIN + i4 + 3) * L_ + lt + l];
        __nv_bfloat16 r[4] = {__float2bfloat16(v0), __float2bfloat16(v1),
                              __float2bfloat16(v2), __float2bfloat16(v3)};
        char* base = smc + ((i4 >> 6) ? 16384 : 0);
        *(uint2*)(base + SWZ128(l * 128 + (i4 & 63) * 2)) = *(uint2*)r;
    }
    // ---- load W stacked [384 rows][i] bf16, halves by i ----
    for (int it = tid; it < 12288; it += 256) {
        int p = it >> 12, rem = it & 4095;
        int o = rem >> 5, i4 = (rem & 31) * 4;
        const float* wp = (p == 0) ? wq : (p == 1) ? wk : wv;
        float4 v = *(const float4*)&wp[o * 128 + i4];
        __nv_bfloat16 r[4] = {__float2bfloat16(v.x), __float2bfloat16(v.y),
                              __float2bfloat16(v.z), __float2bfloat16(v.w)};
        int row = p * 128 + o;
        char* base = smc + 32768 + ((i4 >> 6) ? 49152 : 0);
        *(uint2*)(base + SWZ128(row * 128 + (i4 & 63) * 2)) = *(uint2*)r;
    }
    __syncthreads();

    const uint32_t arow = (lane & 7) + ((lane >> 3) & 1) * 8;
    const uint32_t acol = (lane >> 4) * 16;
    const uint32_t brow_lo  = (lane & 7) + ((lane >> 4) << 3);
    const uint32_t bcol_sel = ((lane >> 3) & 1) * 16;

    const int c0 = wid * 16 + g;  // channel within projection (rows g, g+8)

#pragma unroll
    for (int p = 0; p < 3; p++) {
        const int mt = wid + p * 8;      // m-tile: rows mt*16.. = proj p, ch wid*16..
        float acc[16][4];
#pragma unroll
        for (int i = 0; i < 16; i++)
#pragma unroll
            for (int j = 0; j < 4; j++) acc[i][j] = 0.f;

#pragma unroll
        for (int kc = 0; kc < 8; kc++) {
            const uint32_t wbase = smb + 32768 + ((kc >> 2) ? 49152 : 0);
            const uint32_t xbase = smb + ((kc >> 2) ? 16384 : 0);
            const int ks = kc & 3;
            uint32_t a4[4];
            ldsm_x4(a4, wbase + SWZ128((mt * 16 + arow) * 128 + ks * 32 + acol));
#pragma unroll
            for (int np = 0; np < 8; np++) {
                uint32_t b4[4];
                ldsm_x4(b4, xbase + SWZ128((np * 16 + brow_lo) * 128 + ks * 32 + bcol_sel));
                mma_bf16(acc[2 * np],     a4, b4);
                mma_bf16(acc[2 * np + 1], a4, b4 + 2);
            }
        }

        // ---- epilogue ----
        const float* bias = (p == 0) ? bq : (p == 1) ? bk : bv;
        const float b0 = bias[c0], b1 = bias[c0 + 8];
        if (p < 2) {
            __nv_bfloat16* dst = (p == 0) ? g_qbf : g_kbf;
            const float s = (p == 0) ? QSCALE : 1.0f;
#pragma unroll
            for (int nt = 0; nt < 16; nt++) {
                const size_t l0 = (size_t)(b * L_ + lt + nt * 8 + tig * 2) * 128;
                dst[l0 + c0]           = __float2bfloat16((acc[nt][0] + b0) * s);
                dst[l0 + 128 + c0]     = __float2bfloat16((acc[nt][1] + b0) * s);
                dst[l0 + c0 + 8]       = __float2bfloat16((acc[nt][2] + b1) * s);
                dst[l0 + 128 + c0 + 8] = __float2bfloat16((acc[nt][3] + b1) * s);
            }
        } else {
#pragma unroll
            for (int nt = 0; nt < 16; nt++) {
                const int l0 = lt + nt * 8 + tig * 2;
                __nv_bfloat162 v0 = __floats2bfloat162_rn(acc[nt][0] + b0, acc[nt][1] + b0);
                __nv_bfloat162 v1 = __floats2bfloat162_rn(acc[nt][2] + b1, acc[nt][3] + b1);
                *(__nv_bfloat162*)&g_vbf[(size_t)(b * COUT + c0) * L_ + l0]     = v0;
                *(__nv_bfloat162*)&g_vbf[(size_t)(b * COUT + c0 + 8) * L_ + l0] = v1;
            }
        }
    }
}

// ---------------------------------------------------------------------------
// Kernel 2: FMHA via warp-level HMMA (unchanged structure; exp2 softmax).
// ---------------------------------------------------------------------------
#define OFF_Q   0
#define OFF_K   16384
#define OFF_V   49152
#define SMEM_ATTN 81920

__device__ __forceinline__ void load_kv_tile(uint32_t smb, int tid, int b, int head,
                                             int kt, int s)
{
    const char* kb = (const char*)g_kbf;
    const uint32_t kdst = smb + OFF_K + s * 16384;
    for (int i = tid; i < 1024; i += 256) {
        int r = i >> 3, ch = i & 7;
        const char* src = kb + ((size_t)(b * L_ + kt + r) * COUT + head * DK) * 2 + ch * 16;
        cp16(kdst + SWZ128(r * 128 + ch * 16), src);
    }
    const char* vb = (const char*)g_vbf;
    const uint32_t vdst = smb + OFF_V + s * 16384;
    for (int i = tid; i < 1024; i += 256) {
        int half = i >> 9, rem = i & 511;
        int d = rem >> 3, ch = rem & 7;
        const char* src = vb + ((size_t)(b * COUT + head * DK + d) * L_ + kt + half * 64 + ch * 8) * 2;
        cp16(vdst + half * 8192 + SWZ128(d * 128 + ch * 16), src);
    }
}

__global__ __launch_bounds__(256, 1)
void attn_mma_kernel()
{
    extern __shared__ char smc[];
    const uint32_t smb = smem_u32(smc);

    const int tid  = threadIdx.x;
    const int wid  = tid >> 5;
    const int lane = tid & 31;
    const int qt   = blockIdx.x * 128;
    const int head = blockIdx.y;
    const int b    = blockIdx.z;

    const int g   = lane >> 2;
    const int tig = lane & 3;

    {
        const char* qb = (const char*)g_qbf;
        for (int i = tid; i < 1024; i += 256) {
            int r = i >> 3, ch = i & 7;
            const char* src = qb + ((size_t)(b * L_ + qt + r) * COUT + head * DK) * 2 + ch * 16;
            cp16(smb + OFF_Q + SWZ128(r * 128 + ch * 16), src);
        }
        load_kv_tile(smb, tid, b, head, 0, 0);
        asm volatile("cp.async.commit_group;" ::: "memory");
    }

    uint32_t qhr[4][4];
    float O[8][4];
#pragma unroll
    for (int i = 0; i < 8; i++)
#pragma unroll
        for (int j = 0; j < 4; j++) O[i][j] = 0.f;
    float rsum0 = 0.f, rsum1 = 0.f;

    const uint32_t brow_lo  = (lane & 7) + ((lane >> 4) << 3);
    const uint32_t bcol_sel = ((lane >> 3) & 1) * 16;

    for (int t = 0; t < 32; t++) {
        __syncthreads();
        if (t + 1 < 32) {
            load_kv_tile(smb, tid, b, head, (t + 1) * 128, (t + 1) & 1);
            asm volatile("cp.async.commit_group;" ::: "memory");
            asm volatile("cp.async.wait_group 1;" ::: "memory");
        } else {
            asm volatile("cp.async.wait_group 0;" ::: "memory");
        }
        __syncthreads();

        if (t == 0) {
            const uint32_t arow = wid * 16 + (lane & 7) + ((lane >> 3) & 1) * 8;
#pragma unroll
            for (int ks = 0; ks < 4; ks++) {
                uint32_t colb = ks * 32 + (lane >> 4) * 16;
                ldsm_x4(qhr[ks], smb + OFF_Q + SWZ128(arow * 128 + colb));
            }
        }

        const uint32_t kbase = smb + OFF_K + (t & 1) * 16384;
        const uint32_t vbase = smb + OFF_V + (t & 1) * 16384;

        float S[16][4];
#pragma unroll
        for (int i = 0; i < 16; i++)
#pragma unroll
            for (int j = 0; j < 4; j++) S[i][j] = 0.f;

#pragma unroll
        for (int ks = 0; ks < 4; ks++) {
#pragma unroll
            for (int np = 0; np < 8; np++) {
                uint32_t bh[4];
                uint32_t row = np * 16 + brow_lo;
                ldsm_x4(bh, kbase + SWZ128(row * 128 + ks * 32 + bcol_sel));
                mma_bf16(S[2 * np],     qhr[ks], bh);
                mma_bf16(S[2 * np + 1], qhr[ks], bh + 2);
            }
        }

        uint32_t pf[16][2];
#pragma unroll
        for (int nt = 0; nt < 16; nt++) {
            float p0 = ex2f(S[nt][0]);
            float p1 = ex2f(S[nt][1]);
            float p2 = ex2f(S[nt][2]);
            float p3 = ex2f(S[nt][3]);
            __nv_bfloat162 lo2 = __floats2bfloat162_rn(p0, p1);
            __nv_bfloat162 hi2 = __floats2bfloat162_rn(p2, p3);
            pf[nt][0] = *(uint32_t*)&lo2;
            pf[nt][1] = *(uint32_t*)&hi2;
            rsum0 += __bfloat162float(lo2.x) + __bfloat162float(lo2.y);
            rsum1 += __bfloat162float(hi2.x) + __bfloat162float(hi2.y);
        }

#pragma unroll
        for (int kk = 0; kk < 8; kk++) {
            uint32_t afr[4] = {pf[2 * kk][0], pf[2 * kk][1], pf[2 * kk + 1][0], pf[2 * kk + 1][1]};
            uint32_t vb2 = vbase + ((kk >= 4) ? 8192 : 0);
#pragma unroll
            for (int dp = 0; dp < 4; dp++) {
                uint32_t vfr[4];
                uint32_t row = dp * 16 + brow_lo;
                ldsm_x4(vfr, vb2 + SWZ128(row * 128 + (kk & 3) * 32 + bcol_sel));
                mma_bf16(O[2 * dp],     afr, vfr);
                mma_bf16(O[2 * dp + 1], afr, vfr + 2);
            }
        }
    }

    rsum0 += __shfl_xor_sync(0xffffffffu, rsum0, 1);
    rsum0 += __shfl_xor_sync(0xffffffffu, rsum0, 2);
    rsum1 += __shfl_xor_sync(0xffffffffu, rsum1, 1);
    rsum1 += __shfl_xor_sync(0xffffffffu, rsum1, 2);
    const float inv0 = 1.f / rsum0;
    const float inv1 = 1.f / rsum1;

    __syncthreads();
    float* Ost = (float*)smc;  // 64 x 132 fp32
    const int q0 = wid * 16 + g;
#pragma unroll
    for (int dt = 0; dt < 8; dt++) {
        int d = dt * 8 + 2 * tig;
        Ost[(d)     * 132 + q0]     = O[dt][0] * inv0;
        Ost[(d + 1) * 132 + q0]     = O[dt][1] * inv0;
        Ost[(d)     * 132 + q0 + 8] = O[dt][2] * inv1;
        Ost[(d + 1) * 132 + q0 + 8] = O[dt][3] * inv1;
    }
    __syncthreads();

    float* og = g_att + (size_t)(b * COUT + head * DK) * L_ + qt;
    for (int i = tid; i < 64 * 128; i += 256) {
        int d = i >> 7, l = i & 127;
        og[(size_t)d * L_ + l] = Ost[d * 132 + l];
    }
}

// ---------------------------------------------------------------------------
// Kernel 3: fc_out + BN + PReLU via hi/lo bf16 HMMA (3-product compensation).
// smem: Ahi @0/16384, Alo @32768/49152, Fhi @65536/81920, Flo @98304/114688.
// ---------------------------------------------------------------------------
#define FC_SMEM 131072
__global__ __launch_bounds__(256, 1)
void fc_hmma(const float* __restrict__ fcw, const float* __restrict__ fcb,
             const float* __restrict__ gamma, const float* __restrict__ beta,
             const float* __restrict__ mean,  const float* __restrict__ var,
             const float* __restrict__ prelu, float* __restrict__ y)
{
    extern __shared__ char smc[];
    const uint32_t smb = smem_u32(smc);
    const int tid = threadIdx.x, wid = tid >> 5, lane = tid & 31;
    const int rt = blockIdx.x * 128;
    const int g = lane >> 2, tig = lane & 3;

    // ---- load + hi/lo split: A rows (g_att flat [16384][128]) and F ----
    for (int it = tid; it < 4096; it += 256) {
        int r = it >> 5, w4 = (it & 31) * 4;
        float4 v = *(const float4*)&g_att[(size_t)(rt + r) * 128 + w4];
        __nv_bfloat16 hi[4], lo[4];
        hi[0] = __float2bfloat16(v.x); lo[0] = __float2bfloat16(v.x - __bfloat162float(hi[0]));
        hi[1] = __float2bfloat16(v.y); lo[1] = __float2bfloat16(v.y - __bfloat162float(hi[1]));
        hi[2] = __float2bfloat16(v.z); lo[2] = __float2bfloat16(v.z - __bfloat162float(hi[2]));
        hi[3] = __float2bfloat16(v.w); lo[3] = __float2bfloat16(v.w - __bfloat162float(hi[3]));
        uint32_t off = SWZ128(r * 128 + (w4 & 63) * 2) + ((w4 >> 6) ? 16384 : 0);
        *(uint2*)(smc + off)         = *(uint2*)hi;
        *(uint2*)(smc + 32768 + off) = *(uint2*)lo;
    }
    for (int it = tid; it < 4096; it += 256) {
        int o = it >> 5, w4 = (it & 31) * 4;
        float4 v = *(const float4*)&fcw[o * 128 + w4];
        __nv_bfloat16 hi[4], lo[4];
        hi[0] = __float2bfloat16(v.x); lo[0] = __float2bfloat16(v.x - __bfloat162float(hi[0]));
        hi[1] = __float2bfloat16(v.y); lo[1] = __float2bfloat16(v.y - __bfloat162float(hi[1]));
        hi[2] = __float2bfloat16(v.z); lo[2] = __float2bfloat16(v.z - __bfloat162float(hi[2]));
        hi[3] = __float2bfloat16(v.w); lo[3] = __float2bfloat16(v.w - __bfloat162float(hi[3]));
        uint32_t off = SWZ128(o * 128 + (w4 & 63) * 2) + ((w4 >> 6) ? 16384 : 0);
        *(uint2*)(smc + 65536 + off) = *(uint2*)hi;
        *(uint2*)(smc + 98304 + off) = *(uint2*)lo;
    }
    __syncthreads();

    const uint32_t arow = wid * 16 + (lane & 7) + ((lane >> 3) & 1) * 8;
    const uint32_t acol = (lane >> 4) * 16;
    const uint32_t brow_lo  = (lane & 7) + ((lane >> 4) << 3);
    const uint32_t bcol_sel = ((lane >> 3) & 1) * 16;

    float acc[16][4];
#pragma unroll
    for (int i = 0; i < 16; i++)
#pragma unroll
        for (int j = 0; j < 4; j++) acc[i][j] = 0.f;

#pragma unroll
    for (int kc = 0; kc < 8; kc++) {
        const uint32_t hoff = ((kc >> 2) ? 16384 : 0);
        const int ks = kc & 3;
        uint32_t ah[4], al[4];
        uint32_t aoff = SWZ128(arow * 128 + ks * 32 + acol) + hoff;
        ldsm_x4(ah, smb + aoff);
        ldsm_x4(al, smb + 32768 + aoff);

        uint32_t bh[8][4], bl[8][4];
#pragma unroll
        for (int np = 0; np < 8; np++) {
            uint32_t boff = SWZ128((np * 16 + brow_lo) * 128 + ks * 32 + bcol_sel) + hoff;
            ldsm_x4(bh[np], smb + 65536 + boff);
            ldsm_x4(bl[np], smb + 98304 + boff);
        }
        // hh (16 independent), then hl, then lh — no back-to-back acc deps
#pragma unroll
        for (int np = 0; np < 8; np++) {
            mma_bf16(acc[2 * np],     ah, bh[np]);
            mma_bf16(acc[2 * np + 1], ah, bh[np] + 2);
        }
#pragma unroll
        for (int np = 0; np < 8; np++) {
            mma_bf16(acc[2 * np],     ah, bl[np]);
            mma_bf16(acc[2 * np + 1], ah, bl[np] + 2);
        }
#pragma unroll
        for (int np = 0; np < 8; np++) {
            mma_bf16(acc[2 * np],     al, bh[np]);
            mma_bf16(acc[2 * np + 1], al, bh[np] + 2);
        }
    }

    // ---- epilogue: bias + BN + PReLU ----
    const float slope = prelu[0];
    const int r0 = rt + wid * 16 + g;
#pragma unroll
    for (int half = 0; half < 2; half++) {
        const int r = r0 + 8 * half;
        const int c = (r >> 5) & 127;
        const float sc = rsqrtf(var[c] + BN_EPS) * gamma[c];
        const float sh = beta[c] - mean[c] * sc;
#pragma unroll
        for (int nt = 0; nt < 16; nt++) {
            const int o = nt * 8 + tig * 2;
            float v0 = (acc[nt][2 * half]     + fcb[o])     * sc + sh;
            float v1 = (acc[nt][2 * half + 1] + fcb[o + 1]) * sc + sh;
            v0 = (v0 > 0.f) ? v0 : slope * v0;
            v1 = (v1 > 0.f) ? v1 : slope * v1;
            *(float2*)&y[(size_t)r * 128 + o] = make_float2(v0, v1);
        }
    }
}

// ---------------------------------------------------------------------------
extern "C" void kernel_launch(void* const* d_in, const int* in_sizes, int n_in,
                              void* d_out, int out_size)
{
    const float* x     = (const float*)d_in[0];
    const float* wq    = (const float*)d_in[1];
    const float* bq    = (const float*)d_in[2];
    const float* wk    = (const float*)d_in[3];
    const float* bk    = (const float*)d_in[4];
    const float* wv    = (const float*)d_in[5];
    const float* bv    = (const float*)d_in[6];
    const float* fc_w  = (const float*)d_in[7];
    const float* fc_b  = (const float*)d_in[8];
    const float* gam   = (const float*)d_in[9];
    const float* bet   = (const float*)d_in[10];
    const float* mean  = (const float*)d_in[11];
    const float* var   = (const float*)d_in[12];
    const float* prelu = (const float*)d_in[13];
    float* y = (float*)d_out;

    cudaFuncSetAttribute(qkv_hmma, cudaFuncAttributeMaxDynamicSharedMemorySize, QKV_SMEM);
    cudaFuncSetAttribute(attn_mma_kernel, cudaFuncAttributeMaxDynamicSharedMemorySize, SMEM_ATTN);
    cudaFuncSetAttribute(fc_hmma, cudaFuncAttributeMaxDynamicSharedMemorySize, FC_SMEM);

    qkv_hmma<<<dim3(32, B_), 256, QKV_SMEM>>>(x, wq, bq, wk, bk, wv, bv);
    attn_mma_kernel<<<dim3(L_ / 128, NH, B_), 256, SMEM_ATTN>>>();
    fc_hmma<<<128, 256, FC_SMEM>>>(fc_w, fc_b, gam, bet, mean, var, prelu, y);
}